// round 11
// baseline (speedup 1.0000x reference)
#include <cuda_runtime.h>
#include <cuda_bf16.h>
#include <cstdint>

// Problem constants
#define Bn   16
#define HW   4096
#define IMG  64
#define DIMC 256
#define NHn  8
#define CPHn 8
#define QKVC 192
#define CRn  64
#define SCALE 0.17677669529663687f   // 32^-0.5

// Scratch
__device__ float g_qkv[(size_t)Bn * QKVC * HW];            // 50 MB fp32
__device__ __nv_bfloat16 g_xhi[(size_t)Bn * DIMC * HW];    // 32 MB
__device__ __nv_bfloat16 g_xlo[(size_t)Bn * DIMC * HW];    // 32 MB
__device__ __nv_bfloat16 g_ohi[(size_t)Bn * CRn * HW];     // 8 MB
__device__ __nv_bfloat16 g_olo[(size_t)Bn * CRn * HW];     // 8 MB

// ---------------------------------------------------------------------------
// PTX helpers
// ---------------------------------------------------------------------------
__device__ __forceinline__ void mma_bf16(float* c, const uint32_t* a, const uint32_t* b) {
    asm volatile(
        "mma.sync.aligned.m16n8k16.row.col.f32.bf16.bf16.f32 "
        "{%0,%1,%2,%3}, {%4,%5,%6,%7}, {%8,%9}, {%0,%1,%2,%3};"
        : "+f"(c[0]), "+f"(c[1]), "+f"(c[2]), "+f"(c[3])
        : "r"(a[0]), "r"(a[1]), "r"(a[2]), "r"(a[3]), "r"(b[0]), "r"(b[1]));
}
__device__ __forceinline__ void ldm_x4(uint32_t* r, uint32_t addr) {
    asm volatile("ldmatrix.sync.aligned.m8n8.x4.shared.b16 {%0,%1,%2,%3}, [%4];"
        : "=r"(r[0]), "=r"(r[1]), "=r"(r[2]), "=r"(r[3]) : "r"(addr));
}
__device__ __forceinline__ void ldm_x4_t(uint32_t* r, uint32_t addr) {
    asm volatile("ldmatrix.sync.aligned.m8n8.x4.trans.shared.b16 {%0,%1,%2,%3}, [%4];"
        : "=r"(r[0]), "=r"(r[1]), "=r"(r[2]), "=r"(r[3]) : "r"(addr));
}
__device__ __forceinline__ void cp16(uint32_t dst, const void* src) {
    asm volatile("cp.async.cg.shared.global [%0], [%1], 16;" :: "r"(dst), "l"(src));
}
#define CP_COMMIT() asm volatile("cp.async.commit_group;" ::: "memory")
#define CP_WAIT0()  asm volatile("cp.async.wait_group 0;" ::: "memory")

// ---------------------------------------------------------------------------
// Kernel 0: split X -> bf16 hi/lo
// ---------------------------------------------------------------------------
__global__ __launch_bounds__(256) void split_x_kernel(const float* __restrict__ X)
{
    size_t gid = (size_t)blockIdx.x * 256 + threadIdx.x;
    float4 v = ((const float4*)X)[gid];
    __nv_bfloat16 h0 = __float2bfloat16(v.x), h1 = __float2bfloat16(v.y);
    __nv_bfloat16 h2 = __float2bfloat16(v.z), h3 = __float2bfloat16(v.w);
    __nv_bfloat16 l0 = __float2bfloat16(v.x - __bfloat162float(h0));
    __nv_bfloat16 l1 = __float2bfloat16(v.y - __bfloat162float(h1));
    __nv_bfloat16 l2 = __float2bfloat16(v.z - __bfloat162float(h2));
    __nv_bfloat16 l3 = __float2bfloat16(v.w - __bfloat162float(h3));
    __nv_bfloat162 hA(h0, h1), hB(h2, h3), lA(l0, l1), lB(l2, l3);
    ((uint2*)g_xhi)[gid] = make_uint2(*(uint32_t*)&hA, *(uint32_t*)&hB);
    ((uint2*)g_xlo)[gid] = make_uint2(*(uint32_t*)&lA, *(uint32_t*)&lB);
}

// ---------------------------------------------------------------------------
// Kernel 1: QKV GEMM (unchanged from R10)
// ---------------------------------------------------------------------------
#define AST   264
#define AROWB (AST * 2)
#define A_ELE (2 * 64 * AST)
#define BSTn  136
#define BROWB (BSTn * 2)
#define BCHUNKB (32 * BROWB)
#define BBUFB   (2 * BCHUNKB)
#define QKV_SMEM (A_ELE * 2 + 2 * BBUFB)

__global__ __launch_bounds__(256) void qkv_mma_kernel(
    const float* __restrict__ W, const float* __restrict__ bias)
{
    extern __shared__ __nv_bfloat16 sm[];
    __nv_bfloat16* As = sm;
    __nv_bfloat16* Bs = sm + A_ELE;

    const int tid  = threadIdx.x;
    const int wid  = tid >> 5;
    const int lane = tid & 31;
    const int wm   = wid & 1;
    const int wn   = wid >> 1;
    const int g    = lane >> 2;
    const int tg   = lane & 3;

    const int m0g  = blockIdx.y * 64;
    const int col0 = blockIdx.x * 128;
    const int b    = col0 >> 12;
    const int nb   = col0 & 4095;

    const __nv_bfloat16* xh = g_xhi + ((size_t)b * DIMC) * HW + nb;
    const __nv_bfloat16* xl = g_xlo + ((size_t)b * DIMC) * HW + nb;

    const uint32_t bs_b = (uint32_t)__cvta_generic_to_shared(Bs);

#pragma unroll
    for (int it = 0; it < 4; it++) {
        int idx = tid + it * 256;
        int ss = idx >> 9, r = (idx >> 4) & 31, q = idx & 15;
        const __nv_bfloat16* src = (ss ? xl : xh) + (size_t)r * HW + q * 8;
        cp16(bs_b + ss * BCHUNKB + r * BROWB + q * 16, src);
    }
    CP_COMMIT();

#pragma unroll
    for (int i = 0; i < 32; i++) {
        int idx = tid + i * 256;
        int m  = idx >> 7;
        int kp = idx & 127;
        float2 w = *(const float2*)(W + (size_t)(m0g + m) * DIMC + kp * 2);
        __nv_bfloat16 h0 = __float2bfloat16(w.x);
        __nv_bfloat16 h1 = __float2bfloat16(w.y);
        __nv_bfloat16 l0 = __float2bfloat16(w.x - __bfloat162float(h0));
        __nv_bfloat16 l1 = __float2bfloat16(w.y - __bfloat162float(h1));
        __nv_bfloat162 hh(h0, h1), ll(l0, l1);
        *(uint32_t*)&As[(size_t)m * AST + kp * 2]        = *(uint32_t*)&hh;
        *(uint32_t*)&As[(size_t)(64 + m) * AST + kp * 2] = *(uint32_t*)&ll;
    }

    const uint32_t a_lane = (uint32_t)__cvta_generic_to_shared(As)
                          + (lane & 15) * AROWB + (lane >> 4) * 16;
    const uint32_t b_lane = bs_b + (lane & 15) * BROWB + (lane >> 4) * 16;

    float acc[2][4][4];
#pragma unroll
    for (int mt = 0; mt < 2; mt++)
#pragma unroll
        for (int nt = 0; nt < 4; nt++)
#pragma unroll
            for (int r = 0; r < 4; r++) acc[mt][nt][r] = 0.f;

    for (int kc = 0; kc < 8; kc++) {
        const int buf = kc & 1;
        CP_WAIT0();
        __syncthreads();

        if (kc < 7) {
#pragma unroll
            for (int it = 0; it < 4; it++) {
                int idx = tid + it * 256;
                int ss = idx >> 9, r = (idx >> 4) & 31, q = idx & 15;
                const __nv_bfloat16* src = (ss ? xl : xh) + (size_t)((kc + 1) * 32 + r) * HW + q * 8;
                cp16(bs_b + (buf ^ 1) * BBUFB + ss * BCHUNKB + r * BROWB + q * 16, src);
            }
            CP_COMMIT();
        }

#pragma unroll
        for (int ks = 0; ks < 2; ks++) {
            const int k0 = kc * 32 + ks * 16;
            uint32_t ah[2][4], al[2][4];
#pragma unroll
            for (int mt = 0; mt < 2; mt++) {
                uint32_t a0 = a_lane + (wm * 32 + mt * 16) * AROWB + k0 * 2;
                ldm_x4(ah[mt], a0);
                ldm_x4(al[mt], a0 + 64 * AROWB);
            }
            uint32_t bh[2][4], bl[2][4];
#pragma unroll
            for (int j = 0; j < 2; j++) {
                uint32_t b0 = b_lane + buf * BBUFB + (ks * 16) * BROWB + (wn * 32 + j * 16) * 2;
                ldm_x4_t(bh[j], b0);
                ldm_x4_t(bl[j], b0 + BCHUNKB);
            }
#pragma unroll
            for (int mt = 0; mt < 2; mt++)
#pragma unroll
                for (int nt = 0; nt < 4; nt++) {
                    const uint32_t* bhp = &bh[nt >> 1][(nt & 1) * 2];
                    const uint32_t* blp = &bl[nt >> 1][(nt & 1) * 2];
                    mma_bf16(acc[mt][nt], ah[mt], bhp);
                    mma_bf16(acc[mt][nt], al[mt], bhp);
                    mma_bf16(acc[mt][nt], ah[mt], blp);
                }
        }
    }

#pragma unroll
    for (int mt = 0; mt < 2; mt++) {
        int r0 = m0g + wm * 32 + mt * 16 + g;
        int r1 = r0 + 8;
        float bv0 = bias[r0], bv1 = bias[r1];
        float* d0 = g_qkv + (size_t)b * (QKVC * HW) + (size_t)r0 * HW + nb;
        float* d1 = g_qkv + (size_t)b * (QKVC * HW) + (size_t)r1 * HW + nb;
#pragma unroll
        for (int nt = 0; nt < 4; nt++) {
            int c = wn * 32 + nt * 8 + tg * 2;
            *(float2*)(d0 + c) = make_float2(acc[mt][nt][0] + bv0, acc[mt][nt][1] + bv0);
            *(float2*)(d1 + c) = make_float2(acc[mt][nt][2] + bv1, acc[mt][nt][3] + bv1);
        }
    }
}

// ---------------------------------------------------------------------------
// Kernel 2: fused unfold-conv + slide attention (RESTRUCTURED for occupancy)
// - q streamed per-g with prefetch (frees ~28 live regs)
// - rpb*qsum applied post-loop
// - __launch_bounds__(256, 2): target 2 blocks/SM
// ---------------------------------------------------------------------------
#define TS 32
#define HAL (TS + 2)
#define HALN (HAL * HAL)

__global__ __launch_bounds__(256, 2) void attn_kernel(
    const float* __restrict__ w1g, const float* __restrict__ b0g,
    const float* __restrict__ b1g, const float* __restrict__ rpbg)
{
    __shared__ float hs[CPHn][HAL][HAL];
    __shared__ float w1p[72 * 12];
    __shared__ float rpb[9];

    const int tile = blockIdx.x;
    const int n    = blockIdx.y;
    const int b    = blockIdx.z;
    const int ty0  = (tile >> 1) * TS;
    const int tx0  = (tile & 1) * TS;
    const int tid  = threadIdx.x;
    const int tx   = tid & 31;
    const int tr   = tid >> 5;

    for (int i = tid; i < 648; i += 256) {
        int e = i / 9, t = i - e * 9;
        w1p[e * 12 + t] = w1g[i];
    }
    if (tid < 72) w1p[tid * 12 + 9] = b0g[tid] + b1g[tid];
    if (tid < 9)  rpb[tid] = rpbg[n * 9 + tid];

    const size_t hbase = (size_t)b * (QKVC * HW) + (size_t)(n * 24) * HW;
    const float* base_q = g_qkv + hbase;
    const float* base_k = g_qkv + hbase + (size_t)8  * HW;
    const float* base_v = g_qkv + hbase + (size_t)16 * HW;

    const int hw0 = (ty0 + tr * 4) * IMG + (tx0 + tx);

    // ---- load kk halo ----
#pragma unroll
    for (int g = 0; g < CPHn; g++) {
        const float* src = base_k + (size_t)g * HW;
        for (int i = tid; i < HALN; i += 256) {
            int hy = i / HAL, hx = i - hy * HAL;
            int gy = ty0 - 1 + hy, gx = tx0 - 1 + hx;
            bool ok = (unsigned)gy < 64u && (unsigned)gx < 64u;
            ((float*)hs)[g * HALN + i] = ok ? src[gy * IMG + gx] : 0.f;
        }
    }
    __syncthreads();

    float lg[4][9];
#pragma unroll
    for (int p = 0; p < 4; p++)
#pragma unroll
        for (int j = 0; j < 9; j++) lg[p][j] = 0.f;
    float qsum[4] = {0.f, 0.f, 0.f, 0.f};

    // prefetch q for g=0
    float qv[4];
    {
        const float* qp = base_q + hw0;
#pragma unroll
        for (int p = 0; p < 4; p++) qv[p] = qp[p * IMG];
    }

    // ---- K phase: q streamed per g ----
#pragma unroll
    for (int g = 0; g < CPHn; g++) {
        float qn[4];
        if (g < CPHn - 1) {
            const float* qp = base_q + (size_t)(g + 1) * HW + hw0;
#pragma unroll
            for (int p = 0; p < 4; p++) qn[p] = qp[p * IMG];
        }
        float qc[4];
#pragma unroll
        for (int p = 0; p < 4; p++) {
            qc[p] = qv[p] * SCALE;
            qsum[p] += qc[p];
        }

        float t[6][3];
#pragma unroll
        for (int rr = 0; rr < 6; rr++)
#pragma unroll
            for (int cc = 0; cc < 3; cc++)
                t[rr][cc] = hs[g][tr * 4 + rr][tx + cc];
#pragma unroll
        for (int j = 0; j < 9; j++) {
            const int jh = j / 3, jw = j % 3;
            const int wb = (g * 9 + j) * 12;
            float4 wa = *(const float4*)&w1p[wb];
            float4 wc = *(const float4*)&w1p[wb + 4];
            float4 we = *(const float4*)&w1p[wb + 8];
#pragma unroll
            for (int p = 0; p < 4; p++) {
                float kj = t[p + jh][jw] + we.y;
                kj = fmaf(wa.x, t[p][0], kj);
                kj = fmaf(wa.y, t[p][1], kj);
                kj = fmaf(wa.z, t[p][2], kj);
                kj = fmaf(wa.w, t[p + 1][0], kj);
                kj = fmaf(wc.x, t[p + 1][1], kj);
                kj = fmaf(wc.y, t[p + 1][2], kj);
                kj = fmaf(wc.z, t[p + 2][0], kj);
                kj = fmaf(wc.w, t[p + 2][1], kj);
                kj = fmaf(we.x, t[p + 2][2], kj);
                lg[p][j] = fmaf(qc[p], kj, lg[p][j]);
            }
        }
#pragma unroll
        for (int p = 0; p < 4; p++) qv[p] = qn[p];
    }

    // ---- rpb fixup + softmax ----
#pragma unroll
    for (int p = 0; p < 4; p++) {
#pragma unroll
        for (int j = 0; j < 9; j++) lg[p][j] = fmaf(rpb[j], qsum[p], lg[p][j]);
        float mx = lg[p][0];
#pragma unroll
        for (int j = 1; j < 9; j++) mx = fmaxf(mx, lg[p][j]);
        float s = 0.f;
#pragma unroll
        for (int j = 0; j < 9; j++) { lg[p][j] = __expf(lg[p][j] - mx); s += lg[p][j]; }
        float inv = 1.f / s;
#pragma unroll
        for (int j = 0; j < 9; j++) lg[p][j] *= inv;
    }

    // ---- reload halo with vv ----
    __syncthreads();
#pragma unroll
    for (int g = 0; g < CPHn; g++) {
        const float* src = base_v + (size_t)g * HW;
        for (int i = tid; i < HALN; i += 256) {
            int hy = i / HAL, hx = i - hy * HAL;
            int gy = ty0 - 1 + hy, gx = tx0 - 1 + hx;
            bool ok = (unsigned)gy < 64u && (unsigned)gx < 64u;
            ((float*)hs)[g * HALN + i] = ok ? src[gy * IMG + gx] : 0.f;
        }
    }
    __syncthreads();

    // ---- V phase ----
    const size_t obase = (size_t)b * (CRn * HW) + (size_t)(n * CPHn) * HW + hw0;
#pragma unroll
    for (int g = 0; g < CPHn; g++) {
        float t[6][3];
#pragma unroll
        for (int rr = 0; rr < 6; rr++)
#pragma unroll
            for (int cc = 0; cc < 3; cc++)
                t[rr][cc] = hs[g][tr * 4 + rr][tx + cc];
        float og[4] = {0.f, 0.f, 0.f, 0.f};
#pragma unroll
        for (int j = 0; j < 9; j++) {
            const int jh = j / 3, jw = j % 3;
            const int wb = (g * 9 + j) * 12;
            float4 wa = *(const float4*)&w1p[wb];
            float4 wc = *(const float4*)&w1p[wb + 4];
            float4 we = *(const float4*)&w1p[wb + 8];
#pragma unroll
            for (int p = 0; p < 4; p++) {
                float vj = t[p + jh][jw] + we.y;
                vj = fmaf(wa.x, t[p][0], vj);
                vj = fmaf(wa.y, t[p][1], vj);
                vj = fmaf(wa.z, t[p][2], vj);
                vj = fmaf(wa.w, t[p + 1][0], vj);
                vj = fmaf(wc.x, t[p + 1][1], vj);
                vj = fmaf(wc.y, t[p + 1][2], vj);
                vj = fmaf(wc.z, t[p + 2][0], vj);
                vj = fmaf(wc.w, t[p + 2][1], vj);
                vj = fmaf(we.x, t[p + 2][2], vj);
                og[p] = fmaf(lg[p][j], vj, og[p]);
            }
        }
        __nv_bfloat16* oph = g_ohi + obase + (size_t)g * HW;
        __nv_bfloat16* opl = g_olo + obase + (size_t)g * HW;
#pragma unroll
        for (int p = 0; p < 4; p++) {
            __nv_bfloat16 h = __float2bfloat16(og[p]);
            __nv_bfloat16 l = __float2bfloat16(og[p] - __bfloat162float(h));
            oph[p * IMG] = h;
            opl[p * IMG] = l;
        }
    }
}

// ---------------------------------------------------------------------------
// Kernel 3: projection GEMM (unchanged from R10)
// ---------------------------------------------------------------------------
#define AST2  72
#define AROW2B (AST2 * 2)
#define A2_ELE (2 * 64 * AST2)
#define BFULLB (64 * BROWB)
#define PROJ_SMEM (A2_ELE * 2 + 2 * BFULLB)

__global__ __launch_bounds__(256) void proj_mma_kernel(
    const float* __restrict__ W, const float* __restrict__ bias,
    float* __restrict__ OUT)
{
    extern __shared__ __nv_bfloat16 sm2[];
    __nv_bfloat16* As = sm2;
    __nv_bfloat16* Bs = sm2 + A2_ELE;

    const int tid  = threadIdx.x;
    const int wid  = tid >> 5;
    const int lane = tid & 31;
    const int wm   = wid & 1;
    const int wn   = wid >> 1;
    const int g    = lane >> 2;
    const int tg   = lane & 3;

    const int m0g  = blockIdx.y * 64;
    const int col0 = blockIdx.x * 128;
    const int b    = col0 >> 12;
    const int nb   = col0 & 4095;

    const __nv_bfloat16* xh = g_ohi + ((size_t)b * CRn) * HW + nb;
    const __nv_bfloat16* xl = g_olo + ((size_t)b * CRn) * HW + nb;
    const uint32_t bs_b = (uint32_t)__cvta_generic_to_shared(Bs);

#pragma unroll
    for (int it = 0; it < 8; it++) {
        int idx = tid + it * 256;
        int ss = idx >> 10, r = (idx >> 4) & 63, q = idx & 15;
        const __nv_bfloat16* src = (ss ? xl : xh) + (size_t)r * HW + q * 8;
        cp16(bs_b + ss * BFULLB + r * BROWB + q * 16, src);
    }
    CP_COMMIT();

#pragma unroll
    for (int i = 0; i < 8; i++) {
        int idx = tid + i * 256;
        int m  = idx >> 5;
        int kp = idx & 31;
        float2 w = *(const float2*)(W + (size_t)(m0g + m) * CRn + kp * 2);
        __nv_bfloat16 h0 = __float2bfloat16(w.x);
        __nv_bfloat16 h1 = __float2bfloat16(w.y);
        __nv_bfloat16 l0 = __float2bfloat16(w.x - __bfloat162float(h0));
        __nv_bfloat16 l1 = __float2bfloat16(w.y - __bfloat162float(h1));
        __nv_bfloat162 hh(h0, h1), ll(l0, l1);
        *(uint32_t*)&As[(size_t)m * AST2 + kp * 2]        = *(uint32_t*)&hh;
        *(uint32_t*)&As[(size_t)(64 + m) * AST2 + kp * 2] = *(uint32_t*)&ll;
    }

    const uint32_t a_lane = (uint32_t)__cvta_generic_to_shared(As)
                          + (lane & 15) * AROW2B + (lane >> 4) * 16;
    const uint32_t b_lane = bs_b + (lane & 15) * BROWB + (lane >> 4) * 16;

    float acc[2][4][4];
#pragma unroll
    for (int mt = 0; mt < 2; mt++)
#pragma unroll
        for (int nt = 0; nt < 4; nt++)
#pragma unroll
            for (int r = 0; r < 4; r++) acc[mt][nt][r] = 0.f;

    CP_WAIT0();
    __syncthreads();

#pragma unroll
    for (int ks = 0; ks < 4; ks++) {
        const int k0 = ks * 16;
        uint32_t ah[2][4], al[2][4];
#pragma unroll
        for (int mt = 0; mt < 2; mt++) {
            uint32_t a0 = a_lane + (wm * 32 + mt * 16) * AROW2B + k0 * 2;
            ldm_x4(ah[mt], a0);
            ldm_x4(al[mt], a0 + 64 * AROW2B);
        }
        uint32_t bh[2][4], bl[2][4];
#pragma unroll
        for (int j = 0; j < 2; j++) {
            uint32_t b0 = b_lane + k0 * BROWB + (wn * 32 + j * 16) * 2;
            ldm_x4_t(bh[j], b0);
            ldm_x4_t(bl[j], b0 + BFULLB);
        }
#pragma unroll
        for (int mt = 0; mt < 2; mt++)
#pragma unroll
            for (int nt = 0; nt < 4; nt++) {
                const uint32_t* bhp = &bh[nt >> 1][(nt & 1) * 2];
                const uint32_t* blp = &bl[nt >> 1][(nt & 1) * 2];
                mma_bf16(acc[mt][nt], ah[mt], bhp);
                mma_bf16(acc[mt][nt], al[mt], bhp);
                mma_bf16(acc[mt][nt], ah[mt], blp);
            }
    }

#pragma unroll
    for (int mt = 0; mt < 2; mt++) {
        int r0 = m0g + wm * 32 + mt * 16 + g;
        int r1 = r0 + 8;
        float bv0 = bias[r0], bv1 = bias[r1];
        float* d0 = OUT + (size_t)b * (DIMC * HW) + (size_t)r0 * HW + nb;
        float* d1 = OUT + (size_t)b * (DIMC * HW) + (size_t)r1 * HW + nb;
#pragma unroll
        for (int nt = 0; nt < 4; nt++) {
            int c = wn * 32 + nt * 8 + tg * 2;
            *(float2*)(d0 + c) = make_float2(acc[mt][nt][0] + bv0, acc[mt][nt][1] + bv0);
            *(float2*)(d1 + c) = make_float2(acc[mt][nt][2] + bv1, acc[mt][nt][3] + bv1);
        }
    }
}

// ---------------------------------------------------------------------------
// Launch. Inputs: 0:x 1:H22 2:W22 3:rpi 4:rct 5:qkv_w 6:qkv_b 7:dep_conv_b
// 8:dep_conv1_w 9:dep_conv1_b 10:rpb_table 11:proj_w 12:proj_b
// ---------------------------------------------------------------------------
extern "C" void kernel_launch(void* const* d_in, const int* in_sizes, int n_in,
                              void* d_out, int out_size)
{
    const float* x      = (const float*)d_in[0];
    const float* qkv_w  = (const float*)d_in[5];
    const float* qkv_b  = (const float*)d_in[6];
    const float* dcb    = (const float*)d_in[7];
    const float* dc1w   = (const float*)d_in[8];
    const float* dc1b   = (const float*)d_in[9];
    const float* rpb    = (const float*)d_in[10];
    const float* proj_w = (const float*)d_in[11];
    const float* proj_b = (const float*)d_in[12];
    float* out = (float*)d_out;

    static int smem_set = 0;
    if (!smem_set) {
        cudaFuncSetAttribute(qkv_mma_kernel, cudaFuncAttributeMaxDynamicSharedMemorySize, QKV_SMEM);
        cudaFuncSetAttribute(proj_mma_kernel, cudaFuncAttributeMaxDynamicSharedMemorySize, PROJ_SMEM);
        smem_set = 1;
    }

    split_x_kernel<<<16384, 256>>>(x);
    qkv_mma_kernel<<<dim3(512, 3), 256, QKV_SMEM>>>(qkv_w, qkv_b);
    attn_kernel<<<dim3(4, NHn, Bn), 256>>>(dc1w, dcb, dc1b, rpb);
    proj_mma_kernel<<<dim3(512, 4), 256, PROJ_SMEM>>>(proj_w, proj_b, out);
}